// round 9
// baseline (speedup 1.0000x reference)
#include <cuda_runtime.h>
#include <cuda_bf16.h>
#include <cuda_fp16.h>
#include <math.h>
#include <stdint.h>

#define N_NODES 131072
#define N_EDGES 524288
#define N_GRAPHS 4096
#define D 256
#define EPS 1e-10f

// ---------------- scratch (device globals; no allocation allowed) ----------
__device__ float g_hx0[N_NODES * D];
__device__ float g_hx1[N_NODES * D];          // aliases x
__device__ float g_e[N_EDGES * D];
__device__ float g_agg[N_NODES * D];
__device__ float g_t[N_NODES * 2 * D];
__device__ float g_xconv[N_NODES * D];
__device__ float g_g1[N_GRAPHS * 4 * D];
__device__ float g_g2[N_GRAPHS * 4 * D];
__device__ float g_hs[N_GRAPHS * D];
__device__ float g_cs[N_GRAPHS * D];
__device__ float g_qstar[N_GRAPHS * 2 * D];
__device__ float g_prod[N_NODES];
__device__ float g_m[N_GRAPHS];
__device__ float g_norm[N_GRAPHS];
__device__ float g_w1t[512 * 256];            // gin_w1^T  [N=512, K=256]
__device__ float g_w2t[256 * 512];            // gin_w2^T  [N=256, K=512]
__device__ float g_wip[2 * 768 * 256];        // permuted gru_wih
__device__ float g_whp[2 * 768 * 256];        // permuted gru_whh

// ---------------- helpers ----------------
__device__ __forceinline__ uint32_t smem_u32(const void* p) {
    uint32_t a;
    asm("{ .reg .u64 t; cvta.to.shared.u64 t, %1; cvt.u32.u64 %0, t; }" : "=r"(a) : "l"(p));
    return a;
}
__device__ __forceinline__ void atomicMaxFloat(float* addr, float val) {
    int* ia = (int*)addr;
    int cur = __float_as_int(*(volatile float*)addr);
    while (__int_as_float(cur) < val) {
        int old = atomicCAS(ia, cur, __float_as_int(val));
        if (old == cur) break;
        cur = old;
    }
}
__device__ __forceinline__ float sigmoidf_(float x) { return 1.0f / (1.0f + expf(-x)); }
__device__ __forceinline__ void mma_f16(float* c, const uint32_t* a, const uint32_t* b) {
    asm volatile(
        "mma.sync.aligned.m16n8k16.row.col.f32.f16.f16.f32 "
        "{%0,%1,%2,%3}, {%4,%5,%6,%7}, {%8,%9}, {%0,%1,%2,%3};"
        : "+f"(c[0]), "+f"(c[1]), "+f"(c[2]), "+f"(c[3])
        : "r"(a[0]), "r"(a[1]), "r"(a[2]), "r"(a[3]), "r"(b[0]), "r"(b[1]));
}
__device__ __forceinline__ void ldsm_x4(uint32_t* r, uint32_t saddr) {
    asm volatile("ldmatrix.sync.aligned.m8n8.x4.shared.b16 {%0,%1,%2,%3}, [%4];"
                 : "=r"(r[0]), "=r"(r[1]), "=r"(r[2]), "=r"(r[3]) : "r"(saddr));
}
__device__ __forceinline__ void ldsm_x2(uint32_t* r, uint32_t saddr) {
    asm volatile("ldmatrix.sync.aligned.m8n8.x2.shared.b16 {%0,%1}, [%2];"
                 : "=r"(r[0]), "=r"(r[1]) : "r"(saddr));
}
__device__ __forceinline__ uint32_t pack_h2(float x, float y) {
    __half2 h = __float22half2_rn(make_float2(x, y));
    return *(uint32_t*)&h;
}
__device__ __forceinline__ float gru_one(float ivr, float ivz, float ivn,
                                         float hvr, float hvz, float hvn, float hp) {
    float r = sigmoidf_(ivr + hvr);
    float z = sigmoidf_(ivz + hvz);
    float nn = tanhf(ivn + r * hvn);
    return (1.f - z) * nn + z * hp;
}

// ---------------- generic fp16 GEMM: C[M,N] = A @ B^T + bias --------------
static constexpr int GEMM_RSTRIDE_B = 80;
static constexpr int GEMM_A_BYTES = 128 * GEMM_RSTRIDE_B;
static constexpr int GEMM_B_BYTES = 256 * GEMM_RSTRIDE_B;
static constexpr int GEMM_BUF_BYTES = GEMM_A_BYTES + GEMM_B_BYTES;
static constexpr int GEMM_SMEM = 2 * GEMM_BUF_BYTES;
static constexpr int GEMM_TPB = 512;

template <bool RELU>
__global__ __launch_bounds__(GEMM_TPB, 1) void mma_gemm_kernel(
    const float* __restrict__ A, const float* __restrict__ B,
    const float* __restrict__ bias, float* __restrict__ C,
    int M, int N, int K) {
    extern __shared__ char smc[];
    const int tid = threadIdx.x;
    const int lane = tid & 31;
    const int warp = tid >> 5;
    const int wm = warp & 1;
    const int wn = warp >> 1;
    const int m0 = blockIdx.y * 128;
    const int n0 = blockIdx.x * 256;
    const uint32_t sbase = smem_u32(smc);
    const int ar = tid >> 3, ac = tid & 7;
    const int g = lane >> 3, r8 = lane & 7;
    const uint32_t a_l = (uint32_t)((wm * 64 + (g & 1) * 8 + r8) * GEMM_RSTRIDE_B +
                                    (g >> 1) * 16);
    const uint32_t b_l = (uint32_t)((wn * 32 + (g & 1) * 8 + r8) * GEMM_RSTRIDE_B +
                                    (g >> 1) * 16) + GEMM_A_BYTES;

    float acc[4][4][4];
#pragma unroll
    for (int i = 0; i < 4; i++)
#pragma unroll
        for (int j = 0; j < 4; j++)
#pragma unroll
            for (int q = 0; q < 4; q++) acc[i][j][q] = 0.f;

    const int niter = K >> 5;
    float4 pa[2], pb[4];

#define LDG_TILE(k0i)                                                              \
    do {                                                                           \
        const float* Ag = A + (size_t)m0 * K + (k0i) * 32;                         \
        const float* Bg = B + (size_t)n0 * K + (k0i) * 32;                         \
        _Pragma("unroll")                                                          \
        for (int i = 0; i < 2; i++)                                                \
            pa[i] = *(const float4*)&Ag[(size_t)(ar + i * 64) * K + ac * 4];       \
        _Pragma("unroll")                                                          \
        for (int i = 0; i < 4; i++)                                                \
            pb[i] = *(const float4*)&Bg[(size_t)(ar + i * 64) * K + ac * 4];       \
    } while (0)

#define STS_TILE(buf)                                                              \
    do {                                                                           \
        char* Ab_ = smc + (buf) * GEMM_BUF_BYTES;                                  \
        char* Bb_ = Ab_ + GEMM_A_BYTES;                                            \
        _Pragma("unroll")                                                          \
        for (int i = 0; i < 2; i++) {                                              \
            uint2* p = (uint2*)(Ab_ + (ar + i * 64) * GEMM_RSTRIDE_B + ac * 8);    \
            *p = make_uint2(pack_h2(pa[i].x, pa[i].y), pack_h2(pa[i].z, pa[i].w)); \
        }                                                                          \
        _Pragma("unroll")                                                          \
        for (int i = 0; i < 4; i++) {                                              \
            uint2* p = (uint2*)(Bb_ + (ar + i * 64) * GEMM_RSTRIDE_B + ac * 8);    \
            *p = make_uint2(pack_h2(pb[i].x, pb[i].y), pack_h2(pb[i].z, pb[i].w)); \
        }                                                                          \
    } while (0)

    LDG_TILE(0);
    STS_TILE(0);
    __syncthreads();
    if (niter > 1) LDG_TILE(1);

    for (int k0i = 0; k0i < niter; k0i++) {
        if (k0i + 1 < niter) STS_TILE((k0i + 1) & 1);
        if (k0i + 2 < niter) LDG_TILE(k0i + 2);

        const uint32_t base = sbase + (uint32_t)((k0i & 1) * GEMM_BUF_BYTES);
        const uint32_t aaddr = base + a_l;
        const uint32_t baddr = base + b_l;
#pragma unroll
        for (int ks = 0; ks < 2; ks++) {
            uint32_t a[4][4];
#pragma unroll
            for (int i = 0; i < 4; i++)
                ldsm_x4(a[i], aaddr + (uint32_t)(i * 16 * GEMM_RSTRIDE_B + ks * 32));
            uint32_t b[4][2];
#pragma unroll
            for (int jj = 0; jj < 2; jj++) {
                uint32_t t[4];
                ldsm_x4(t, baddr + (uint32_t)(jj * 16 * GEMM_RSTRIDE_B + ks * 32));
                b[2 * jj][0] = t[0]; b[2 * jj][1] = t[2];
                b[2 * jj + 1][0] = t[1]; b[2 * jj + 1][1] = t[3];
            }
#pragma unroll
            for (int i = 0; i < 4; i++)
#pragma unroll
                for (int j = 0; j < 4; j++) mma_f16(acc[i][j], a[i], b[j]);
        }
        __syncthreads();
    }

#pragma unroll
    for (int i = 0; i < 4; i++) {
        int mr = m0 + wm * 64 + i * 16 + (lane >> 2);
#pragma unroll
        for (int j = 0; j < 4; j++) {
            int nc = n0 + wn * 32 + j * 8 + (lane & 3) * 2;
            float b0 = bias[nc], b1 = bias[nc + 1];
            float v0 = acc[i][j][0] + b0;
            float v1 = acc[i][j][1] + b1;
            float v2 = acc[i][j][2] + b0;
            float v3 = acc[i][j][3] + b1;
            if (RELU) {
                v0 = fmaxf(v0, 0.f); v1 = fmaxf(v1, 0.f);
                v2 = fmaxf(v2, 0.f); v3 = fmaxf(v3, 0.f);
            }
            *(float2*)&C[(size_t)mr * N + nc] = make_float2(v0, v1);
            *(float2*)&C[(size_t)(mr + 8) * N + nc] = make_float2(v2, v3);
        }
    }
#undef LDG_TILE
#undef STS_TILE
}

// ---------------- fused GRU step: h = GRU(x, h) ----------------------------
// Computes gi = x@Wi^T+bi, gh = h@Wh^T+bh and the gate, in one kernel.
// Wi/Wh are PRE-PERMUTED: row c' = (d/8)*24 + gate*8 + (d%8), so a warp's
// 24-col span holds all 3 gates for 8 d's. Block: 128 rows x 32 d, 8 warps
// (2m x 4n), K=256 fixed. In-place h update (blocks own disjoint rows).
static constexpr int FG_RSTR = 80;
static constexpr int FG_A_BYTES = 128 * FG_RSTR;       // 10240
static constexpr int FG_B_BYTES = 96 * FG_RSTR;        // 7680
static constexpr int FG_BUF = 2 * FG_A_BYTES + 2 * FG_B_BYTES;  // 35840
static constexpr int FG_SMEM = 2 * FG_BUF;             // 71680

__global__ __launch_bounds__(256, 1) void fused_gru_kernel(
    const float* __restrict__ Ax, const float* __restrict__ Wi,
    const float* __restrict__ Wh, const float* __restrict__ bih,
    const float* __restrict__ bhh, float* __restrict__ h,
    float* __restrict__ agg_out) {
    extern __shared__ char smc[];
    const int tid = threadIdx.x;
    const int lane = tid & 31;
    const int warp = tid >> 5;
    const int wm = warp & 1;          // 2 warps along M (64 rows each)
    const int wn = warp >> 1;         // 4 warps along d (8 d's each)
    const int m0 = blockIdx.y * 128;
    const int bx = blockIdx.x;        // d-block: 32 d's; perm-col base bx*96
    const uint32_t sbase = smem_u32(smc);
    const int ar = tid >> 3, ac = tid & 7;    // staging: 32 rows/pass
    const int g = lane >> 3, r8 = lane & 7;

    const uint32_t a_l = (uint32_t)((wm * 64 + (g & 1) * 8 + r8) * FG_RSTR +
                                    (g >> 1) * 16);
    const uint32_t b4_l = (uint32_t)(2 * FG_A_BYTES +
                                     (wn * 24 + (g & 1) * 8 + r8) * FG_RSTR +
                                     (g >> 1) * 16);
    const uint32_t b2_l = (uint32_t)(2 * FG_A_BYTES +
                                     (wn * 24 + 16 + (lane & 7)) * FG_RSTR +
                                     ((lane >> 3) & 1) * 16);

    float acci[4][3][4], acch[4][3][4];
#pragma unroll
    for (int i = 0; i < 4; i++)
#pragma unroll
        for (int j = 0; j < 3; j++)
#pragma unroll
            for (int q = 0; q < 4; q++) { acci[i][j][q] = 0.f; acch[i][j][q] = 0.f; }

    float4 pa1[4], pa2[4], pb1[3], pb2[3];

#define FLDG(k0i)                                                                  \
    do {                                                                           \
        const float* A1 = Ax + (size_t)m0 * 256 + (k0i) * 32;                      \
        const float* A2 = h + (size_t)m0 * 256 + (k0i) * 32;                       \
        const float* B1 = Wi + (size_t)(bx * 96) * 256 + (k0i) * 32;               \
        const float* B2 = Wh + (size_t)(bx * 96) * 256 + (k0i) * 32;               \
        _Pragma("unroll")                                                          \
        for (int i = 0; i < 4; i++) {                                              \
            pa1[i] = *(const float4*)&A1[(size_t)(ar + i * 32) * 256 + ac * 4];    \
            pa2[i] = *(const float4*)&A2[(size_t)(ar + i * 32) * 256 + ac * 4];    \
        }                                                                          \
        _Pragma("unroll")                                                          \
        for (int i = 0; i < 3; i++) {                                              \
            pb1[i] = *(const float4*)&B1[(size_t)(ar + i * 32) * 256 + ac * 4];    \
            pb2[i] = *(const float4*)&B2[(size_t)(ar + i * 32) * 256 + ac * 4];    \
        }                                                                          \
    } while (0)

#define FSTS(buf)                                                                  \
    do {                                                                           \
        char* base_ = smc + (buf) * FG_BUF;                                        \
        _Pragma("unroll")                                                          \
        for (int i = 0; i < 4; i++) {                                              \
            uint2* p1 = (uint2*)(base_ + (ar + i * 32) * FG_RSTR + ac * 8);        \
            *p1 = make_uint2(pack_h2(pa1[i].x, pa1[i].y),                          \
                             pack_h2(pa1[i].z, pa1[i].w));                         \
            uint2* p2 = (uint2*)(base_ + FG_A_BYTES +                              \
                                 (ar + i * 32) * FG_RSTR + ac * 8);                \
            *p2 = make_uint2(pack_h2(pa2[i].x, pa2[i].y),                          \
                             pack_h2(pa2[i].z, pa2[i].w));                         \
        }                                                                          \
        _Pragma("unroll")                                                          \
        for (int i = 0; i < 3; i++) {                                              \
            uint2* p1 = (uint2*)(base_ + 2 * FG_A_BYTES +                          \
                                 (ar + i * 32) * FG_RSTR + ac * 8);                \
            *p1 = make_uint2(pack_h2(pb1[i].x, pb1[i].y),                          \
                             pack_h2(pb1[i].z, pb1[i].w));                         \
            uint2* p2 = (uint2*)(base_ + 2 * FG_A_BYTES + FG_B_BYTES +             \
                                 (ar + i * 32) * FG_RSTR + ac * 8);                \
            *p2 = make_uint2(pack_h2(pb2[i].x, pb2[i].y),                          \
                             pack_h2(pb2[i].z, pb2[i].w));                         \
        }                                                                          \
    } while (0)

    FLDG(0);
    FSTS(0);
    __syncthreads();
    FLDG(1);

    const int niter = 8;  // K=256
    for (int k0i = 0; k0i < niter; k0i++) {
        if (k0i + 1 < niter) FSTS((k0i + 1) & 1);
        if (k0i + 2 < niter) FLDG(k0i + 2);

        const uint32_t base = sbase + (uint32_t)((k0i & 1) * FG_BUF);
#pragma unroll
        for (int ks = 0; ks < 2; ks++) {
            uint32_t a1[4][4], a2[4][4];
#pragma unroll
            for (int i = 0; i < 4; i++) {
                uint32_t off = (uint32_t)(i * 16 * FG_RSTR + ks * 32);
                ldsm_x4(a1[i], base + a_l + off);
                ldsm_x4(a2[i], base + FG_A_BYTES + a_l + off);
            }
            uint32_t b1[3][2], b2[3][2];
            {
                uint32_t t[4];
                ldsm_x4(t, base + b4_l + ks * 32);
                b1[0][0] = t[0]; b1[0][1] = t[2];
                b1[1][0] = t[1]; b1[1][1] = t[3];
                uint32_t u[2];
                ldsm_x2(u, base + b2_l + ks * 32);
                b1[2][0] = u[0]; b1[2][1] = u[1];
                ldsm_x4(t, base + FG_B_BYTES + b4_l + ks * 32);
                b2[0][0] = t[0]; b2[0][1] = t[2];
                b2[1][0] = t[1]; b2[1][1] = t[3];
                ldsm_x2(u, base + FG_B_BYTES + b2_l + ks * 32);
                b2[2][0] = u[0]; b2[2][1] = u[1];
            }
#pragma unroll
            for (int i = 0; i < 4; i++)
#pragma unroll
                for (int j = 0; j < 3; j++) {
                    mma_f16(acci[i][j], a1[i], b1[j]);
                    mma_f16(acch[i][j], a2[i], b2[j]);
                }
        }
        __syncthreads();
    }

    // epilogue: apply GRU gate, write h (and agg_out)
    const int d0 = bx * 32 + wn * 8 + (lane & 3) * 2;
    const float2 bir = *(const float2*)&bih[d0];
    const float2 biz = *(const float2*)&bih[256 + d0];
    const float2 bin = *(const float2*)&bih[512 + d0];
    const float2 bhr = *(const float2*)&bhh[d0];
    const float2 bhz = *(const float2*)&bhh[256 + d0];
    const float2 bhn = *(const float2*)&bhh[512 + d0];
#pragma unroll
    for (int i = 0; i < 4; i++) {
        int row = m0 + wm * 64 + i * 16 + (lane >> 2);
        float2 hp1 = *(float2*)&h[(size_t)row * D + d0];
        float2 hp2 = *(float2*)&h[(size_t)(row + 8) * D + d0];
        float2 o1, o2;
        o1.x = gru_one(acci[i][0][0] + bir.x, acci[i][1][0] + biz.x,
                       acci[i][2][0] + bin.x, acch[i][0][0] + bhr.x,
                       acch[i][1][0] + bhz.x, acch[i][2][0] + bhn.x, hp1.x);
        o1.y = gru_one(acci[i][0][1] + bir.y, acci[i][1][1] + biz.y,
                       acci[i][2][1] + bin.y, acch[i][0][1] + bhr.y,
                       acch[i][1][1] + bhz.y, acch[i][2][1] + bhn.y, hp1.y);
        o2.x = gru_one(acci[i][0][2] + bir.x, acci[i][1][2] + biz.x,
                       acci[i][2][2] + bin.x, acch[i][0][2] + bhr.x,
                       acch[i][1][2] + bhz.x, acch[i][2][2] + bhn.x, hp2.x);
        o2.y = gru_one(acci[i][0][3] + bir.y, acci[i][1][3] + biz.y,
                       acci[i][2][3] + bin.y, acch[i][0][3] + bhr.y,
                       acch[i][1][3] + bhz.y, acch[i][2][3] + bhn.y, hp2.y);
        *(float2*)&h[(size_t)row * D + d0] = o1;
        *(float2*)&h[(size_t)(row + 8) * D + d0] = o2;
        if (agg_out) {
            *(float2*)&agg_out[(size_t)row * D + d0] = o1;
            *(float2*)&agg_out[(size_t)(row + 8) * D + d0] = o2;
        }
    }
#undef FLDG
#undef FSTS
}

// ---------------- weight permute for fused GRU ----------------------------
// out row c' = (d/8)*24 + g*8 + d%8  <-  in row g*256 + d
__global__ void permute_w_kernel(const float* __restrict__ in, float* __restrict__ out) {
    int c = blockIdx.x;            // 0..767
    int k = threadIdx.x;           // 0..255
    int gt = (c % 24) >> 3;
    int d = (c / 24) * 8 + (c & 7);
    out[(size_t)c * 256 + k] = in[(size_t)(gt * 256 + d) * 256 + k];
}

// ---------------- weight transpose (tiny, once per launch) ----------------
__global__ void transpose_kernel(const float* __restrict__ in, float* __restrict__ out,
                                 int R, int C) {
    __shared__ float t[32][33];
    int c0 = blockIdx.x * 32, r0 = blockIdx.y * 32;
    for (int i = threadIdx.y; i < 32; i += 8)
        t[i][threadIdx.x] = in[(size_t)(r0 + i) * C + c0 + threadIdx.x];
    __syncthreads();
    for (int i = threadIdx.y; i < 32; i += 8)
        out[(size_t)(c0 + i) * R + r0 + threadIdx.x] = t[threadIdx.x][i];
}

// ---------------- encoders ----------------
__global__ void atom_encode_kernel(const int* __restrict__ xa,
                                   const float* __restrict__ emb,
                                   float* __restrict__ hx0, float* __restrict__ hx1,
                                   float* __restrict__ agg) {
    size_t idx = (size_t)blockIdx.x * blockDim.x + threadIdx.x;
    if (idx >= (size_t)N_NODES * 64) return;
    int n = (int)(idx >> 6);
    int c = (int)(idx & 63);
    float4 acc = make_float4(0.f, 0.f, 0.f, 0.f);
#pragma unroll
    for (int i = 0; i < 9; i++) {
        int t = xa[n * 9 + i];
        const float4 v = *(const float4*)&emb[((size_t)(i * 120 + t)) * D + c * 4];
        acc.x += v.x; acc.y += v.y; acc.z += v.z; acc.w += v.w;
    }
    *(float4*)&hx0[(size_t)n * D + c * 4] = acc;
    *(float4*)&hx1[(size_t)n * D + c * 4] = acc;
    *(float4*)&agg[(size_t)n * D + c * 4] = acc;
}

__global__ void bond_encode_kernel(const int* __restrict__ ea,
                                   const float* __restrict__ emb,
                                   float* __restrict__ e_out) {
    __shared__ float tab[3 * 6 * D];
    for (int i = threadIdx.x; i < 3 * 6 * D; i += blockDim.x) tab[i] = emb[i];
    __syncthreads();
    size_t total = (size_t)N_EDGES * 64;
    size_t stride = (size_t)gridDim.x * blockDim.x;
    for (size_t idx = (size_t)blockIdx.x * blockDim.x + threadIdx.x; idx < total;
         idx += stride) {
        int n = (int)(idx >> 6);
        int c = (int)(idx & 63);
        float4 acc = make_float4(0.f, 0.f, 0.f, 0.f);
#pragma unroll
        for (int i = 0; i < 3; i++) {
            int t = ea[n * 3 + i];
            const float4 v = *(const float4*)&tab[(i * 6 + t) * D + c * 4];
            acc.x += v.x; acc.y += v.y; acc.z += v.z; acc.w += v.w;
        }
        *(float4*)&e_out[(size_t)n * D + c * 4] = acc;
    }
}

// ---------------- edge scatter ----------------
__global__ void edge_scatter_kernel(const int* __restrict__ ei,
                                    const float* __restrict__ x,
                                    const float* __restrict__ e,
                                    float* __restrict__ agg) {
    size_t idx = (size_t)blockIdx.x * blockDim.x + threadIdx.x;
    if (idx >= (size_t)N_EDGES * 64) return;
    int ed = (int)(idx >> 6);
    int c = (int)(idx & 63);
    int s = ei[ed];
    int d = ei[N_EDGES + ed];
    float4 xv = *(const float4*)&x[(size_t)s * D + c * 4];
    float4 ev = *(const float4*)&e[(size_t)ed * D + c * 4];
    float4 m;
    m.x = fmaxf(xv.x + ev.x, 0.f);
    m.y = fmaxf(xv.y + ev.y, 0.f);
    m.z = fmaxf(xv.z + ev.z, 0.f);
    m.w = fmaxf(xv.w + ev.w, 0.f);
    atomicAdd((float4*)&agg[(size_t)d * D + c * 4], m);
}

// ---------------- LSTM gate ----------------
__global__ void lstm_gate_kernel(const float* __restrict__ g1,
                                 const float* __restrict__ g2,
                                 float* __restrict__ hs, float* __restrict__ cs) {
    size_t idx = (size_t)blockIdx.x * blockDim.x + threadIdx.x;
    if (idx >= (size_t)N_GRAPHS * D) return;
    int b = (int)(idx >> 8);
    int d = (int)(idx & 255);
    size_t base = (size_t)b * 4 * D + d;
    float ig = sigmoidf_(g1[base] + g2[base]);
    float fg = sigmoidf_(g1[base + D] + g2[base + D]);
    float gg = tanhf(g1[base + 2 * D] + g2[base + 2 * D]);
    float og = sigmoidf_(g1[base + 3 * D] + g2[base + 3 * D]);
    float c = fg * cs[idx] + ig * gg;
    cs[idx] = c;
    hs[idx] = og * tanhf(c);
}

// ---------------- Set2Set attention ----------------
__global__ void s2s_prep_kernel(float* __restrict__ qstar,
                                const float* __restrict__ hs,
                                float* __restrict__ m, float* __restrict__ norm) {
    size_t i = (size_t)blockIdx.x * blockDim.x + threadIdx.x;
    if (i < N_GRAPHS) { m[i] = -INFINITY; norm[i] = 0.f; }
    if (i < (size_t)N_GRAPHS * D) {
        int b = (int)(i >> 8);
        int d = (int)(i & 255);
        qstar[(size_t)b * 2 * D + d] = hs[i];
        qstar[(size_t)b * 2 * D + D + d] = 0.f;
    }
}

__global__ void attn_prod_kernel(const float* __restrict__ hs,
                                 const float* __restrict__ x,
                                 const int* __restrict__ batch,
                                 float* __restrict__ prod) {
    int warp = (int)(((size_t)blockIdx.x * blockDim.x + threadIdx.x) >> 5);
    int lane = threadIdx.x & 31;
    if (warp >= N_NODES) return;
    int b = batch[warp];
    const float* q = hs + (size_t)b * D;
    const float* xv = x + (size_t)warp * D;
    float s = 0.f;
#pragma unroll
    for (int j = 0; j < D / 32; j++) s += q[lane + j * 32] * xv[lane + j * 32];
#pragma unroll
    for (int o = 16; o; o >>= 1) s += __shfl_xor_sync(0xFFFFFFFFu, s, o);
    if (lane == 0) prod[warp] = s;
}

__global__ void attn_max_kernel(const int* __restrict__ batch,
                                const float* __restrict__ prod,
                                float* __restrict__ m) {
    int n = (int)((size_t)blockIdx.x * blockDim.x + threadIdx.x);
    if (n >= N_NODES) return;
    atomicMaxFloat(&m[batch[n]], prod[n]);
}

__global__ void attn_expnorm_kernel(const int* __restrict__ batch,
                                    float* __restrict__ prod,
                                    const float* __restrict__ m,
                                    float* __restrict__ norm) {
    int n = (int)((size_t)blockIdx.x * blockDim.x + threadIdx.x);
    if (n >= N_NODES) return;
    int b = batch[n];
    float a = expf(prod[n] - m[b]);
    prod[n] = a;
    atomicAdd(&norm[b], a);
}

__global__ void attn_scatter_kernel(const int* __restrict__ batch,
                                    const float* __restrict__ prod,
                                    const float* __restrict__ norm,
                                    const float* __restrict__ x,
                                    float* __restrict__ qstar) {
    size_t idx = (size_t)blockIdx.x * blockDim.x + threadIdx.x;
    if (idx >= (size_t)N_NODES * 64) return;
    int n = (int)(idx >> 6);
    int c = (int)(idx & 63);
    int b = batch[n];
    float coef = prod[n] / (norm[b] + EPS);
    float4 xv = *(const float4*)&x[(size_t)n * D + c * 4];
    float4 v = make_float4(coef * xv.x, coef * xv.y, coef * xv.z, coef * xv.w);
    atomicAdd((float4*)&qstar[(size_t)b * 2 * D + D + c * 4], v);
}

__global__ void fc_kernel(const float* __restrict__ qstar,
                          const float* __restrict__ fw,
                          const float* __restrict__ fb,
                          float* __restrict__ out) {
    int warp = (int)(((size_t)blockIdx.x * blockDim.x + threadIdx.x) >> 5);
    int lane = threadIdx.x & 31;
    if (warp >= N_GRAPHS) return;
    float s = 0.f;
#pragma unroll
    for (int j = 0; j < (2 * D) / 32; j++)
        s += qstar[(size_t)warp * 2 * D + lane + j * 32] * fw[lane + j * 32];
#pragma unroll
    for (int o = 16; o; o >>= 1) s += __shfl_xor_sync(0xFFFFFFFFu, s, o);
    if (lane == 0) out[warp] = s + fb[0];
}

// ---------------- launch ----------------
extern "C" void kernel_launch(void* const* d_in, const int* in_sizes, int n_in,
                              void* d_out, int out_size) {
    const int* x_atoms = (const int*)d_in[0];
    const int* edge_index = (const int*)d_in[1];
    const int* edge_attr = (const int*)d_in[2];
    const int* batch = (const int*)d_in[3];
    const float* atom_emb = (const float*)d_in[4];
    const float* bond_emb = (const float*)d_in[5];
    const float* gin_w1 = (const float*)d_in[6];
    const float* gin_b1 = (const float*)d_in[7];
    const float* gin_w2 = (const float*)d_in[8];
    const float* gin_b2 = (const float*)d_in[9];
    const float* gru_wih = (const float*)d_in[10];
    const float* gru_whh = (const float*)d_in[11];
    const float* gru_bih = (const float*)d_in[12];
    const float* gru_bhh = (const float*)d_in[13];
    const float* lstm_wih = (const float*)d_in[14];
    const float* lstm_whh = (const float*)d_in[15];
    const float* lstm_bih = (const float*)d_in[16];
    const float* lstm_bhh = (const float*)d_in[17];
    const float* fc_w = (const float*)d_in[18];
    const float* fc_b = (const float*)d_in[19];
    float* out = (float*)d_out;

    float *hx0, *hx1, *e, *agg, *t, *xconv, *g1, *g2, *hs, *cs, *qstar,
        *prod, *mbuf, *norm, *w1t, *w2t, *wip, *whp;
    cudaGetSymbolAddress((void**)&hx0, g_hx0);
    cudaGetSymbolAddress((void**)&hx1, g_hx1);
    cudaGetSymbolAddress((void**)&e, g_e);
    cudaGetSymbolAddress((void**)&agg, g_agg);
    cudaGetSymbolAddress((void**)&t, g_t);
    cudaGetSymbolAddress((void**)&xconv, g_xconv);
    cudaGetSymbolAddress((void**)&g1, g_g1);
    cudaGetSymbolAddress((void**)&g2, g_g2);
    cudaGetSymbolAddress((void**)&hs, g_hs);
    cudaGetSymbolAddress((void**)&cs, g_cs);
    cudaGetSymbolAddress((void**)&qstar, g_qstar);
    cudaGetSymbolAddress((void**)&prod, g_prod);
    cudaGetSymbolAddress((void**)&mbuf, g_m);
    cudaGetSymbolAddress((void**)&norm, g_norm);
    cudaGetSymbolAddress((void**)&w1t, g_w1t);
    cudaGetSymbolAddress((void**)&w2t, g_w2t);
    cudaGetSymbolAddress((void**)&wip, g_wip);
    cudaGetSymbolAddress((void**)&whp, g_whp);

    cudaFuncSetAttribute(mma_gemm_kernel<false>,
                         cudaFuncAttributeMaxDynamicSharedMemorySize, GEMM_SMEM);
    cudaFuncSetAttribute(mma_gemm_kernel<true>,
                         cudaFuncAttributeMaxDynamicSharedMemorySize, GEMM_SMEM);
    cudaFuncSetAttribute(fused_gru_kernel,
                         cudaFuncAttributeMaxDynamicSharedMemorySize, FG_SMEM);

    const int TPB = 256;

    transpose_kernel<<<dim3(512 / 32, 256 / 32), dim3(32, 8)>>>(gin_w1, w1t, 256, 512);
    transpose_kernel<<<dim3(256 / 32, 512 / 32), dim3(32, 8)>>>(gin_w2, w2t, 512, 256);
    permute_w_kernel<<<768, 256>>>(gru_wih, wip);
    permute_w_kernel<<<768, 256>>>(gru_wih + 768 * 256, wip + 768 * 256);
    permute_w_kernel<<<768, 256>>>(gru_whh, whp);
    permute_w_kernel<<<768, 256>>>(gru_whh + 768 * 256, whp + 768 * 256);

    atom_encode_kernel<<<(N_NODES * 64) / TPB, TPB>>>(x_atoms, atom_emb, hx0, hx1, agg);
    bond_encode_kernel<<<2048, TPB>>>(edge_attr, bond_emb, e);
    cudaMemsetAsync(hs, 0, (size_t)N_GRAPHS * D * sizeof(float));
    cudaMemsetAsync(cs, 0, (size_t)N_GRAPHS * D * sizeof(float));
    cudaMemsetAsync(qstar, 0, (size_t)N_GRAPHS * 2 * D * sizeof(float));

    for (int layer = 0; layer < 3; layer++) {
        edge_scatter_kernel<<<(N_EDGES * 64) / TPB, TPB>>>(edge_index, hx1, e, agg);
        // GIN MLP (weights pre-transposed to [N,K])
        mma_gemm_kernel<true><<<dim3(512 / 256, N_NODES / 128), GEMM_TPB, GEMM_SMEM>>>(
            agg, w1t, gin_b1, t, N_NODES, 512, 256);
        mma_gemm_kernel<false><<<dim3(256 / 256, N_NODES / 128), GEMM_TPB, GEMM_SMEM>>>(
            t, w2t, gin_b2, xconv, N_NODES, 256, 512);
        // fused GRU layer 0: hx0 = GRU(xconv, hx0)
        fused_gru_kernel<<<dim3(8, N_NODES / 128), 256, FG_SMEM>>>(
            xconv, wip, whp, gru_bih, gru_bhh, hx0, (float*)nullptr);
        // fused GRU layer 1: hx1 = GRU(hx0, hx1)  (+ agg preload for next layer)
        fused_gru_kernel<<<dim3(8, N_NODES / 128), 256, FG_SMEM>>>(
            hx0, wip + 768 * 256, whp + 768 * 256, gru_bih + 768, gru_bhh + 768,
            hx1, layer < 2 ? agg : (float*)nullptr);
    }

    for (int step = 0; step < 3; step++) {
        mma_gemm_kernel<false><<<dim3(1024 / 256, N_GRAPHS / 128), GEMM_TPB, GEMM_SMEM>>>(
            qstar, lstm_wih, lstm_bih, g1, N_GRAPHS, 1024, 512);
        mma_gemm_kernel<false><<<dim3(1024 / 256, N_GRAPHS / 128), GEMM_TPB, GEMM_SMEM>>>(
            hs, lstm_whh, lstm_bhh, g2, N_GRAPHS, 1024, 256);
        lstm_gate_kernel<<<(N_GRAPHS * D) / TPB, TPB>>>(g1, g2, hs, cs);
        s2s_prep_kernel<<<(N_GRAPHS * D) / TPB, TPB>>>(qstar, hs, mbuf, norm);
        attn_prod_kernel<<<(N_NODES * 32) / TPB, TPB>>>(hs, hx1, batch, prod);
        attn_max_kernel<<<N_NODES / TPB, TPB>>>(batch, prod, mbuf);
        attn_expnorm_kernel<<<N_NODES / TPB, TPB>>>(batch, prod, mbuf, norm);
        attn_scatter_kernel<<<(N_NODES * 64) / TPB, TPB>>>(batch, prod, norm, hx1, qstar);
    }

    fc_kernel<<<(N_GRAPHS * 32) / TPB, TPB>>>(qstar, fc_w, fc_b, out);
}

// round 10
// speedup vs baseline: 1.0745x; 1.0745x over previous
#include <cuda_runtime.h>
#include <cuda_bf16.h>
#include <cuda_fp16.h>
#include <math.h>
#include <stdint.h>

#define N_NODES 131072
#define N_EDGES 524288
#define N_GRAPHS 4096
#define D 256
#define EPS 1e-10f

// ---------------- scratch (device globals; no allocation allowed) ----------
__device__ float g_hx0[N_NODES * D];
__device__ float g_hx1[N_NODES * D];          // aliases x
__device__ float g_e[N_EDGES * D];
__device__ float g_agg[N_NODES * D];
__device__ __half g_t16[N_NODES * 2 * D];     // GIN hidden (fp16)
__device__ __half g_xconv16[N_NODES * D];     // GIN out (fp16, GEMM input only)
__device__ __half g_gi16[N_NODES * 3 * D];    // GRU gates (fp16)
__device__ __half g_gh16[N_NODES * 3 * D];
__device__ float g_g1[N_GRAPHS * 4 * D];
__device__ float g_g2[N_GRAPHS * 4 * D];
__device__ float g_hs[N_GRAPHS * D];
__device__ float g_cs[N_GRAPHS * D];
__device__ float g_qstar[N_GRAPHS * 2 * D];
__device__ float g_prod[N_NODES];
__device__ float g_m[N_GRAPHS];
__device__ float g_norm[N_GRAPHS];
__device__ float g_w1t[512 * 256];            // gin_w1^T  [N=512, K=256]
__device__ float g_w2t[256 * 512];            // gin_w2^T  [N=256, K=512]

// ---------------- helpers ----------------
__device__ __forceinline__ uint32_t smem_u32(const void* p) {
    uint32_t a;
    asm("{ .reg .u64 t; cvta.to.shared.u64 t, %1; cvt.u32.u64 %0, t; }" : "=r"(a) : "l"(p));
    return a;
}
__device__ __forceinline__ void atomicMaxFloat(float* addr, float val) {
    int* ia = (int*)addr;
    int cur = __float_as_int(*(volatile float*)addr);
    while (__int_as_float(cur) < val) {
        int old = atomicCAS(ia, cur, __float_as_int(val));
        if (old == cur) break;
        cur = old;
    }
}
__device__ __forceinline__ float sigmoidf_(float x) { return 1.0f / (1.0f + expf(-x)); }
__device__ __forceinline__ void mma_f16(float* c, const uint32_t* a, const uint32_t* b) {
    asm volatile(
        "mma.sync.aligned.m16n8k16.row.col.f32.f16.f16.f32 "
        "{%0,%1,%2,%3}, {%4,%5,%6,%7}, {%8,%9}, {%0,%1,%2,%3};"
        : "+f"(c[0]), "+f"(c[1]), "+f"(c[2]), "+f"(c[3])
        : "r"(a[0]), "r"(a[1]), "r"(a[2]), "r"(a[3]), "r"(b[0]), "r"(b[1]));
}
__device__ __forceinline__ void ldsm_x4(uint32_t* r, uint32_t saddr) {
    asm volatile("ldmatrix.sync.aligned.m8n8.x4.shared.b16 {%0,%1,%2,%3}, [%4];"
                 : "=r"(r[0]), "=r"(r[1]), "=r"(r[2]), "=r"(r[3]) : "r"(saddr));
}
__device__ __forceinline__ uint32_t pack_h2(float x, float y) {
    __half2 h = __float22half2_rn(make_float2(x, y));
    return *(uint32_t*)&h;
}
__device__ __forceinline__ void ld4h(const __half* p, float* o) {
    __half2 a = *(const __half2*)p;
    __half2 b = *(const __half2*)(p + 2);
    o[0] = __low2float(a); o[1] = __high2float(a);
    o[2] = __low2float(b); o[3] = __high2float(b);
}

// ---------------- fp16 tensor-core GEMM: C[M,N] = A @ B^T + bias ----------
// A [M,K] row-major (fp32 or fp16), B [N,K] row-major fp32,
// C [M,N] (fp32 or fp16). M%128==0, N%256==0, K%32==0.
// Block 128x256, BK=32, 16 warps (2m x 8n), warp tile 64x32.
static constexpr int GEMM_RSTRIDE_B = 80;
static constexpr int GEMM_A_BYTES = 128 * GEMM_RSTRIDE_B;
static constexpr int GEMM_B_BYTES = 256 * GEMM_RSTRIDE_B;
static constexpr int GEMM_BUF_BYTES = GEMM_A_BYTES + GEMM_B_BYTES;
static constexpr int GEMM_SMEM = 2 * GEMM_BUF_BYTES;
static constexpr int GEMM_TPB = 512;

template <bool RELU, bool AH, bool CH>
__global__ __launch_bounds__(GEMM_TPB, 1) void mma_gemm_kernel(
    const void* __restrict__ A_, const float* __restrict__ B,
    const float* __restrict__ bias, void* __restrict__ C_,
    int M, int N, int K) {
    extern __shared__ char smc[];
    const int tid = threadIdx.x;
    const int lane = tid & 31;
    const int warp = tid >> 5;
    const int wm = warp & 1;
    const int wn = warp >> 1;
    const int m0 = blockIdx.y * 128;
    const int n0 = blockIdx.x * 256;
    const uint32_t sbase = smem_u32(smc);
    const int ar = tid >> 3, ac = tid & 7;
    const int g = lane >> 3, r8 = lane & 7;
    const uint32_t a_l = (uint32_t)((wm * 64 + (g & 1) * 8 + r8) * GEMM_RSTRIDE_B +
                                    (g >> 1) * 16);
    const uint32_t b_l = (uint32_t)((wn * 32 + (g & 1) * 8 + r8) * GEMM_RSTRIDE_B +
                                    (g >> 1) * 16) + GEMM_A_BYTES;

    float acc[4][4][4];
#pragma unroll
    for (int i = 0; i < 4; i++)
#pragma unroll
        for (int j = 0; j < 4; j++)
#pragma unroll
            for (int q = 0; q < 4; q++) acc[i][j][q] = 0.f;

    const int niter = K >> 5;
    float4 pa[2], pb[4];
    uint2 pa16[2];

#define LDG_TILE(k0i)                                                              \
    do {                                                                           \
        const float* Bg = B + (size_t)n0 * K + (k0i) * 32;                         \
        if (AH) {                                                                  \
            const __half* Ag = (const __half*)A_ + (size_t)m0 * K + (k0i) * 32;    \
            _Pragma("unroll")                                                      \
            for (int i = 0; i < 2; i++)                                            \
                pa16[i] = *(const uint2*)&Ag[(size_t)(ar + i * 64) * K + ac * 4];  \
        } else {                                                                   \
            const float* Ag = (const float*)A_ + (size_t)m0 * K + (k0i) * 32;      \
            _Pragma("unroll")                                                      \
            for (int i = 0; i < 2; i++)                                            \
                pa[i] = *(const float4*)&Ag[(size_t)(ar + i * 64) * K + ac * 4];   \
        }                                                                          \
        _Pragma("unroll")                                                          \
        for (int i = 0; i < 4; i++)                                                \
            pb[i] = *(const float4*)&Bg[(size_t)(ar + i * 64) * K + ac * 4];       \
    } while (0)

#define STS_TILE(buf)                                                              \
    do {                                                                           \
        char* Ab_ = smc + (buf) * GEMM_BUF_BYTES;                                  \
        char* Bb_ = Ab_ + GEMM_A_BYTES;                                            \
        _Pragma("unroll")                                                          \
        for (int i = 0; i < 2; i++) {                                              \
            uint2* p = (uint2*)(Ab_ + (ar + i * 64) * GEMM_RSTRIDE_B + ac * 8);    \
            if (AH) *p = pa16[i];                                                  \
            else                                                                   \
                *p = make_uint2(pack_h2(pa[i].x, pa[i].y),                         \
                                pack_h2(pa[i].z, pa[i].w));                        \
        }                                                                          \
        _Pragma("unroll")                                                          \
        for (int i = 0; i < 4; i++) {                                              \
            uint2* p = (uint2*)(Bb_ + (ar + i * 64) * GEMM_RSTRIDE_B + ac * 8);    \
            *p = make_uint2(pack_h2(pb[i].x, pb[i].y), pack_h2(pb[i].z, pb[i].w)); \
        }                                                                          \
    } while (0)

    LDG_TILE(0);
    STS_TILE(0);
    __syncthreads();
    if (niter > 1) LDG_TILE(1);

    for (int k0i = 0; k0i < niter; k0i++) {
        if (k0i + 1 < niter) STS_TILE((k0i + 1) & 1);
        if (k0i + 2 < niter) LDG_TILE(k0i + 2);

        const uint32_t base = sbase + (uint32_t)((k0i & 1) * GEMM_BUF_BYTES);
        const uint32_t aaddr = base + a_l;
        const uint32_t baddr = base + b_l;
#pragma unroll
        for (int ks = 0; ks < 2; ks++) {
            uint32_t a[4][4];
#pragma unroll
            for (int i = 0; i < 4; i++)
                ldsm_x4(a[i], aaddr + (uint32_t)(i * 16 * GEMM_RSTRIDE_B + ks * 32));
            uint32_t b[4][2];
#pragma unroll
            for (int jj = 0; jj < 2; jj++) {
                uint32_t t[4];
                ldsm_x4(t, baddr + (uint32_t)(jj * 16 * GEMM_RSTRIDE_B + ks * 32));
                b[2 * jj][0] = t[0]; b[2 * jj][1] = t[2];
                b[2 * jj + 1][0] = t[1]; b[2 * jj + 1][1] = t[3];
            }
#pragma unroll
            for (int i = 0; i < 4; i++)
#pragma unroll
                for (int j = 0; j < 4; j++) mma_f16(acc[i][j], a[i], b[j]);
        }
        __syncthreads();
    }

#pragma unroll
    for (int i = 0; i < 4; i++) {
        int mr = m0 + wm * 64 + i * 16 + (lane >> 2);
#pragma unroll
        for (int j = 0; j < 4; j++) {
            int nc = n0 + wn * 32 + j * 8 + (lane & 3) * 2;
            float b0 = bias[nc], b1 = bias[nc + 1];
            float v0 = acc[i][j][0] + b0;
            float v1 = acc[i][j][1] + b1;
            float v2 = acc[i][j][2] + b0;
            float v3 = acc[i][j][3] + b1;
            if (RELU) {
                v0 = fmaxf(v0, 0.f); v1 = fmaxf(v1, 0.f);
                v2 = fmaxf(v2, 0.f); v3 = fmaxf(v3, 0.f);
            }
            if (CH) {
                __half* C = (__half*)C_;
                *(__half2*)&C[(size_t)mr * N + nc] =
                    __float22half2_rn(make_float2(v0, v1));
                *(__half2*)&C[(size_t)(mr + 8) * N + nc] =
                    __float22half2_rn(make_float2(v2, v3));
            } else {
                float* C = (float*)C_;
                *(float2*)&C[(size_t)mr * N + nc] = make_float2(v0, v1);
                *(float2*)&C[(size_t)(mr + 8) * N + nc] = make_float2(v2, v3);
            }
        }
    }
#undef LDG_TILE
#undef STS_TILE
}

// ---------------- weight transpose (tiny, once per launch) ----------------
__global__ void transpose_kernel(const float* __restrict__ in, float* __restrict__ out,
                                 int R, int C) {
    __shared__ float t[32][33];
    int c0 = blockIdx.x * 32, r0 = blockIdx.y * 32;
    for (int i = threadIdx.y; i < 32; i += 8)
        t[i][threadIdx.x] = in[(size_t)(r0 + i) * C + c0 + threadIdx.x];
    __syncthreads();
    for (int i = threadIdx.y; i < 32; i += 8)
        out[(size_t)(c0 + i) * R + r0 + threadIdx.x] = t[threadIdx.x][i];
}

// ---------------- encoders ----------------
__global__ void atom_encode_kernel(const int* __restrict__ xa,
                                   const float* __restrict__ emb,
                                   float* __restrict__ hx0, float* __restrict__ hx1,
                                   float* __restrict__ agg) {
    size_t idx = (size_t)blockIdx.x * blockDim.x + threadIdx.x;
    if (idx >= (size_t)N_NODES * 64) return;
    int n = (int)(idx >> 6);
    int c = (int)(idx & 63);
    float4 acc = make_float4(0.f, 0.f, 0.f, 0.f);
#pragma unroll
    for (int i = 0; i < 9; i++) {
        int t = xa[n * 9 + i];
        const float4 v = *(const float4*)&emb[((size_t)(i * 120 + t)) * D + c * 4];
        acc.x += v.x; acc.y += v.y; acc.z += v.z; acc.w += v.w;
    }
    *(float4*)&hx0[(size_t)n * D + c * 4] = acc;
    *(float4*)&hx1[(size_t)n * D + c * 4] = acc;
    *(float4*)&agg[(size_t)n * D + c * 4] = acc;
}

__global__ void bond_encode_kernel(const int* __restrict__ ea,
                                   const float* __restrict__ emb,
                                   float* __restrict__ e_out) {
    __shared__ float tab[3 * 6 * D];
    for (int i = threadIdx.x; i < 3 * 6 * D; i += blockDim.x) tab[i] = emb[i];
    __syncthreads();
    size_t total = (size_t)N_EDGES * 64;
    size_t stride = (size_t)gridDim.x * blockDim.x;
    for (size_t idx = (size_t)blockIdx.x * blockDim.x + threadIdx.x; idx < total;
         idx += stride) {
        int n = (int)(idx >> 6);
        int c = (int)(idx & 63);
        float4 acc = make_float4(0.f, 0.f, 0.f, 0.f);
#pragma unroll
        for (int i = 0; i < 3; i++) {
            int t = ea[n * 3 + i];
            const float4 v = *(const float4*)&tab[(i * 6 + t) * D + c * 4];
            acc.x += v.x; acc.y += v.y; acc.z += v.z; acc.w += v.w;
        }
        *(float4*)&e_out[(size_t)n * D + c * 4] = acc;
    }
}

// ---------------- edge scatter ----------------
__global__ void edge_scatter_kernel(const int* __restrict__ ei,
                                    const float* __restrict__ x,
                                    const float* __restrict__ e,
                                    float* __restrict__ agg) {
    size_t idx = (size_t)blockIdx.x * blockDim.x + threadIdx.x;
    if (idx >= (size_t)N_EDGES * 64) return;
    int ed = (int)(idx >> 6);
    int c = (int)(idx & 63);
    int s = ei[ed];
    int d = ei[N_EDGES + ed];
    float4 xv = *(const float4*)&x[(size_t)s * D + c * 4];
    float4 ev = *(const float4*)&e[(size_t)ed * D + c * 4];
    float4 m;
    m.x = fmaxf(xv.x + ev.x, 0.f);
    m.y = fmaxf(xv.y + ev.y, 0.f);
    m.z = fmaxf(xv.z + ev.z, 0.f);
    m.w = fmaxf(xv.w + ev.w, 0.f);
    atomicAdd((float4*)&agg[(size_t)d * D + c * 4], m);
}

// ---------------- GRU / LSTM gates ----------------
__global__ void gru_gate_kernel(const __half* __restrict__ gi,
                                const __half* __restrict__ gh,
                                float* __restrict__ hx,
                                float* __restrict__ agg_out) {
    size_t idx = (size_t)blockIdx.x * blockDim.x + threadIdx.x;
    if (idx >= (size_t)N_NODES * 64) return;
    int n = (int)(idx >> 6);
    int c = (int)(idx & 63);
    size_t base = (size_t)n * 3 * D + c * 4;
    float ir[4], iz[4], in_[4], hr[4], hz[4], hn[4];
    ld4h(gi + base, ir); ld4h(gi + base + D, iz); ld4h(gi + base + 2 * D, in_);
    ld4h(gh + base, hr); ld4h(gh + base + D, hz); ld4h(gh + base + 2 * D, hn);
    size_t hidx = (size_t)n * D + c * 4;
    float4 hp = *(const float4*)&hx[hidx];
    float hpv[4] = {hp.x, hp.y, hp.z, hp.w};
    float ov[4];
#pragma unroll
    for (int q = 0; q < 4; q++) {
        float r = sigmoidf_(ir[q] + hr[q]);
        float z = sigmoidf_(iz[q] + hz[q]);
        float nn = tanhf(in_[q] + r * hn[q]);
        ov[q] = (1.0f - z) * nn + z * hpv[q];
    }
    float4 o = make_float4(ov[0], ov[1], ov[2], ov[3]);
    *(float4*)&hx[hidx] = o;
    if (agg_out) *(float4*)&agg_out[hidx] = o;
}

__global__ void lstm_gate_kernel(const float* __restrict__ g1,
                                 const float* __restrict__ g2,
                                 float* __restrict__ hs, float* __restrict__ cs) {
    size_t idx = (size_t)blockIdx.x * blockDim.x + threadIdx.x;
    if (idx >= (size_t)N_GRAPHS * D) return;
    int b = (int)(idx >> 8);
    int d = (int)(idx & 255);
    size_t base = (size_t)b * 4 * D + d;
    float ig = sigmoidf_(g1[base] + g2[base]);
    float fg = sigmoidf_(g1[base + D] + g2[base + D]);
    float gg = tanhf(g1[base + 2 * D] + g2[base + 2 * D]);
    float og = sigmoidf_(g1[base + 3 * D] + g2[base + 3 * D]);
    float c = fg * cs[idx] + ig * gg;
    cs[idx] = c;
    hs[idx] = og * tanhf(c);
}

// ---------------- Set2Set attention ----------------
__global__ void s2s_prep_kernel(float* __restrict__ qstar,
                                const float* __restrict__ hs,
                                float* __restrict__ m, float* __restrict__ norm) {
    size_t i = (size_t)blockIdx.x * blockDim.x + threadIdx.x;
    if (i < N_GRAPHS) { m[i] = -INFINITY; norm[i] = 0.f; }
    if (i < (size_t)N_GRAPHS * D) {
        int b = (int)(i >> 8);
        int d = (int)(i & 255);
        qstar[(size_t)b * 2 * D + d] = hs[i];
        qstar[(size_t)b * 2 * D + D + d] = 0.f;
    }
}

__global__ void attn_prod_kernel(const float* __restrict__ hs,
                                 const float* __restrict__ x,
                                 const int* __restrict__ batch,
                                 float* __restrict__ prod) {
    int warp = (int)(((size_t)blockIdx.x * blockDim.x + threadIdx.x) >> 5);
    int lane = threadIdx.x & 31;
    if (warp >= N_NODES) return;
    int b = batch[warp];
    const float* q = hs + (size_t)b * D;
    const float* xv = x + (size_t)warp * D;
    float s = 0.f;
#pragma unroll
    for (int j = 0; j < D / 32; j++) s += q[lane + j * 32] * xv[lane + j * 32];
#pragma unroll
    for (int o = 16; o; o >>= 1) s += __shfl_xor_sync(0xFFFFFFFFu, s, o);
    if (lane == 0) prod[warp] = s;
}

__global__ void attn_max_kernel(const int* __restrict__ batch,
                                const float* __restrict__ prod,
                                float* __restrict__ m) {
    int n = (int)((size_t)blockIdx.x * blockDim.x + threadIdx.x);
    if (n >= N_NODES) return;
    atomicMaxFloat(&m[batch[n]], prod[n]);
}

__global__ void attn_expnorm_kernel(const int* __restrict__ batch,
                                    float* __restrict__ prod,
                                    const float* __restrict__ m,
                                    float* __restrict__ norm) {
    int n = (int)((size_t)blockIdx.x * blockDim.x + threadIdx.x);
    if (n >= N_NODES) return;
    int b = batch[n];
    float a = expf(prod[n] - m[b]);
    prod[n] = a;
    atomicAdd(&norm[b], a);
}

__global__ void attn_scatter_kernel(const int* __restrict__ batch,
                                    const float* __restrict__ prod,
                                    const float* __restrict__ norm,
                                    const float* __restrict__ x,
                                    float* __restrict__ qstar) {
    size_t idx = (size_t)blockIdx.x * blockDim.x + threadIdx.x;
    if (idx >= (size_t)N_NODES * 64) return;
    int n = (int)(idx >> 6);
    int c = (int)(idx & 63);
    int b = batch[n];
    float coef = prod[n] / (norm[b] + EPS);
    float4 xv = *(const float4*)&x[(size_t)n * D + c * 4];
    float4 v = make_float4(coef * xv.x, coef * xv.y, coef * xv.z, coef * xv.w);
    atomicAdd((float4*)&qstar[(size_t)b * 2 * D + D + c * 4], v);
}

__global__ void fc_kernel(const float* __restrict__ qstar,
                          const float* __restrict__ fw,
                          const float* __restrict__ fb,
                          float* __restrict__ out) {
    int warp = (int)(((size_t)blockIdx.x * blockDim.x + threadIdx.x) >> 5);
    int lane = threadIdx.x & 31;
    if (warp >= N_GRAPHS) return;
    float s = 0.f;
#pragma unroll
    for (int j = 0; j < (2 * D) / 32; j++)
        s += qstar[(size_t)warp * 2 * D + lane + j * 32] * fw[lane + j * 32];
#pragma unroll
    for (int o = 16; o; o >>= 1) s += __shfl_xor_sync(0xFFFFFFFFu, s, o);
    if (lane == 0) out[warp] = s + fb[0];
}

// ---------------- launch ----------------
extern "C" void kernel_launch(void* const* d_in, const int* in_sizes, int n_in,
                              void* d_out, int out_size) {
    const int* x_atoms = (const int*)d_in[0];
    const int* edge_index = (const int*)d_in[1];
    const int* edge_attr = (const int*)d_in[2];
    const int* batch = (const int*)d_in[3];
    const float* atom_emb = (const float*)d_in[4];
    const float* bond_emb = (const float*)d_in[5];
    const float* gin_w1 = (const float*)d_in[6];
    const float* gin_b1 = (const float*)d_in[7];
    const float* gin_w2 = (const float*)d_in[8];
    const float* gin_b2 = (const float*)d_in[9];
    const float* gru_wih = (const float*)d_in[10];
    const float* gru_whh = (const float*)d_in[11];
    const float* gru_bih = (const float*)d_in[12];
    const float* gru_bhh = (const float*)d_in[13];
    const float* lstm_wih = (const float*)d_in[14];
    const float* lstm_whh = (const float*)d_in[15];
    const float* lstm_bih = (const float*)d_in[16];
    const float* lstm_bhh = (const float*)d_in[17];
    const float* fc_w = (const float*)d_in[18];
    const float* fc_b = (const float*)d_in[19];
    float* out = (float*)d_out;

    float *hx0, *hx1, *e, *agg, *g1, *g2, *hs, *cs, *qstar, *prod, *mbuf, *norm,
        *w1t, *w2t;
    __half *t16, *xconv16, *gi16, *gh16;
    cudaGetSymbolAddress((void**)&hx0, g_hx0);
    cudaGetSymbolAddress((void**)&hx1, g_hx1);
    cudaGetSymbolAddress((void**)&e, g_e);
    cudaGetSymbolAddress((void**)&agg, g_agg);
    cudaGetSymbolAddress((void**)&t16, g_t16);
    cudaGetSymbolAddress((void**)&xconv16, g_xconv16);
    cudaGetSymbolAddress((void**)&gi16, g_gi16);
    cudaGetSymbolAddress((void**)&gh16, g_gh16);
    cudaGetSymbolAddress((void**)&g1, g_g1);
    cudaGetSymbolAddress((void**)&g2, g_g2);
    cudaGetSymbolAddress((void**)&hs, g_hs);
    cudaGetSymbolAddress((void**)&cs, g_cs);
    cudaGetSymbolAddress((void**)&qstar, g_qstar);
    cudaGetSymbolAddress((void**)&prod, g_prod);
    cudaGetSymbolAddress((void**)&mbuf, g_m);
    cudaGetSymbolAddress((void**)&norm, g_norm);
    cudaGetSymbolAddress((void**)&w1t, g_w1t);
    cudaGetSymbolAddress((void**)&w2t, g_w2t);

    cudaFuncSetAttribute(mma_gemm_kernel<true, false, true>,
                         cudaFuncAttributeMaxDynamicSharedMemorySize, GEMM_SMEM);
    cudaFuncSetAttribute(mma_gemm_kernel<false, true, true>,
                         cudaFuncAttributeMaxDynamicSharedMemorySize, GEMM_SMEM);
    cudaFuncSetAttribute(mma_gemm_kernel<false, false, true>,
                         cudaFuncAttributeMaxDynamicSharedMemorySize, GEMM_SMEM);
    cudaFuncSetAttribute(mma_gemm_kernel<false, false, false>,
                         cudaFuncAttributeMaxDynamicSharedMemorySize, GEMM_SMEM);

    const int TPB = 256;

    transpose_kernel<<<dim3(512 / 32, 256 / 32), dim3(32, 8)>>>(gin_w1, w1t, 256, 512);
    transpose_kernel<<<dim3(256 / 32, 512 / 32), dim3(32, 8)>>>(gin_w2, w2t, 512, 256);

    atom_encode_kernel<<<(N_NODES * 64) / TPB, TPB>>>(x_atoms, atom_emb, hx0, hx1, agg);
    bond_encode_kernel<<<2048, TPB>>>(edge_attr, bond_emb, e);
    cudaMemsetAsync(hs, 0, (size_t)N_GRAPHS * D * sizeof(float));
    cudaMemsetAsync(cs, 0, (size_t)N_GRAPHS * D * sizeof(float));
    cudaMemsetAsync(qstar, 0, (size_t)N_GRAPHS * 2 * D * sizeof(float));

    for (int layer = 0; layer < 3; layer++) {
        edge_scatter_kernel<<<(N_EDGES * 64) / TPB, TPB>>>(edge_index, hx1, e, agg);
        // GIN MLP: agg(fp32) -> t16 -> xconv16
        mma_gemm_kernel<true, false, true>
            <<<dim3(512 / 256, N_NODES / 128), GEMM_TPB, GEMM_SMEM>>>(
                agg, w1t, gin_b1, t16, N_NODES, 512, 256);
        mma_gemm_kernel<false, true, true>
            <<<dim3(256 / 256, N_NODES / 128), GEMM_TPB, GEMM_SMEM>>>(
                t16, w2t, gin_b2, xconv16, N_NODES, 256, 512);
        // GRU layer 0: gi = xconv16 @ Wi^T, gh = hx0 @ Wh^T (both fp16 out)
        mma_gemm_kernel<false, true, true>
            <<<dim3(768 / 256, N_NODES / 128), GEMM_TPB, GEMM_SMEM>>>(
                xconv16, gru_wih, gru_bih, gi16, N_NODES, 768, 256);
        mma_gemm_kernel<false, false, true>
            <<<dim3(768 / 256, N_NODES / 128), GEMM_TPB, GEMM_SMEM>>>(
                hx0, gru_whh, gru_bhh, gh16, N_NODES, 768, 256);
        gru_gate_kernel<<<(N_NODES * 64) / TPB, TPB>>>(gi16, gh16, hx0,
                                                       (float*)nullptr);
        // GRU layer 1
        mma_gemm_kernel<false, false, true>
            <<<dim3(768 / 256, N_NODES / 128), GEMM_TPB, GEMM_SMEM>>>(
                hx0, gru_wih + 768 * 256, gru_bih + 768, gi16, N_NODES, 768, 256);
        mma_gemm_kernel<false, false, true>
            <<<dim3(768 / 256, N_NODES / 128), GEMM_TPB, GEMM_SMEM>>>(
                hx1, gru_whh + 768 * 256, gru_bhh + 768, gh16, N_NODES, 768, 256);
        gru_gate_kernel<<<(N_NODES * 64) / TPB, TPB>>>(
            gi16, gh16, hx1, layer < 2 ? agg : (float*)nullptr);
    }

    for (int step = 0; step < 3; step++) {
        mma_gemm_kernel<false, false, false>
            <<<dim3(1024 / 256, N_GRAPHS / 128), GEMM_TPB, GEMM_SMEM>>>(
                qstar, lstm_wih, lstm_bih, g1, N_GRAPHS, 1024, 512);
        mma_gemm_kernel<false, false, false>
            <<<dim3(1024 / 256, N_GRAPHS / 128), GEMM_TPB, GEMM_SMEM>>>(
                hs, lstm_whh, lstm_bhh, g2, N_GRAPHS, 1024, 256);
        lstm_gate_kernel<<<(N_GRAPHS * D) / TPB, TPB>>>(g1, g2, hs, cs);
        s2s_prep_kernel<<<(N_GRAPHS * D) / TPB, TPB>>>(qstar, hs, mbuf, norm);
        attn_prod_kernel<<<(N_NODES * 32) / TPB, TPB>>>(hs, hx1, batch, prod);
        attn_max_kernel<<<N_NODES / TPB, TPB>>>(batch, prod, mbuf);
        attn_expnorm_kernel<<<N_NODES / TPB, TPB>>>(batch, prod, mbuf, norm);
        attn_scatter_kernel<<<(N_NODES * 64) / TPB, TPB>>>(batch, prod, norm, hx1, qstar);
    }

    fc_kernel<<<(N_GRAPHS * 32) / TPB, TPB>>>(qstar, fc_w, fc_b, out);
}